// round 2
// baseline (speedup 1.0000x reference)
#include <cuda_runtime.h>

#define D      128
#define K      64
#define N_MAX  200000
#define TEMP   30.0f
#define EPSn   1e-6f
#define CHUNK  32
#define ITERS  11
#define SMEM_BYTES ((D*K + CHUNK*D + CHUNK*K) * 4)

// Scratch (no allocation allowed in kernel_launch)
__device__ float g_dataN[(size_t)N_MAX * D];  // normalized data, 102.4 MB
__device__ float g_muT[D * K];                // normalized mu, transposed [d][k]
__device__ float g_mean[K * D];               // cluster_mean accumulator
__device__ float g_cnt[K];                    // cluster_r accumulator

// ---------------------------------------------------------------------------
// One warp per row: normalize data rows once.
__global__ void norm_data_kernel(const float* __restrict__ x, int N) {
    int w = (blockIdx.x * blockDim.x + threadIdx.x) >> 5;
    int lane = threadIdx.x & 31;
    if (w >= N) return;
    const float4* row = (const float4*)(x + (size_t)w * D);
    float4 v = row[lane];
    float ss = v.x*v.x + v.y*v.y + v.z*v.z + v.w*v.w;
    #pragma unroll
    for (int o = 16; o > 0; o >>= 1) ss += __shfl_xor_sync(0xffffffffu, ss, o);
    float inv = 1.0f / (sqrtf(ss) + EPSn);
    float4 o4 = make_float4(v.x*inv, v.y*inv, v.z*inv, v.w*inv);
    ((float4*)(g_dataN + (size_t)w * D))[lane] = o4;
}

// ---------------------------------------------------------------------------
// Normalize init mu -> g_muT, zero accumulators. grid=K, block=128.
__global__ void init_mu_kernel(const float* __restrict__ init) {
    int k = blockIdx.x;
    int d = threadIdx.x;
    float v = init[k * D + d];
    __shared__ float sred[4];
    float ss = v * v;
    #pragma unroll
    for (int o = 16; o > 0; o >>= 1) ss += __shfl_xor_sync(0xffffffffu, ss, o);
    if ((d & 31) == 0) sred[d >> 5] = ss;
    __syncthreads();
    float tot = sred[0] + sred[1] + sred[2] + sred[3];
    g_muT[d * K + k] = v / (sqrtf(tot) + EPSn);
    g_mean[k * D + d] = 0.0f;
    if (d == 0) g_cnt[k] = 0.0f;
}

// ---------------------------------------------------------------------------
// Fused iteration: dist = dataN @ muT, softmax(TEMP*dist), accumulate
// cluster_r and r^T @ dataN. Optionally writes r to global (last iteration).
// block = 256 threads (8 warps), dynamic smem = 56 KB, grid-strided over
// 32-row chunks.
template<bool WRITE_R>
__global__ void __launch_bounds__(256, 2) iter_kernel(float* __restrict__ r_out,
                                                      int nChunks) {
    extern __shared__ float sm[];
    float* sMuT  = sm;                  // [128][64]
    float* sData = sm + D * K;          // [32][128]
    float* sR    = sData + CHUNK * D;   // [32][64]

    int tid = threadIdx.x;
    int w = tid >> 5, l = tid & 31;

    // stage muT (32 KB)
    #pragma unroll
    for (int i = tid; i < D * K / 4; i += 256)
        ((float4*)sMuT)[i] = ((const float4*)g_muT)[i];

    // phase-C ownership: thread owns cluster kIdx and a 32-wide d-slice
    int kIdx = ((w & 1) << 5) + l;
    int dblk = w >> 1;
    float acc[32];
    #pragma unroll
    for (int j = 0; j < 32; j++) acc[j] = 0.0f;
    float cacc = 0.0f;

    __syncthreads();

    for (int c = blockIdx.x; c < nChunks; c += gridDim.x) {
        // ---- phase A: stage 32 data rows (16 KB) ----
        const float4* src = (const float4*)(g_dataN + (size_t)c * CHUNK * D);
        #pragma unroll
        for (int i = 0; i < 4; i++)
            ((float4*)sData)[tid + 256 * i] = src[tid + 256 * i];
        __syncthreads();

        // ---- phase B: dist + softmax. warp w -> rows 4w..4w+3,
        //      lane l -> clusters 2l, 2l+1 ----
        float ax[4], ay[4];
        #pragma unroll
        for (int i = 0; i < 4; i++) { ax[i] = 0.0f; ay[i] = 0.0f; }
        const float* base = sData + (w * 4) * D;
        #pragma unroll 4
        for (int d = 0; d < D; d++) {
            float2 m = *(const float2*)(sMuT + d * K + 2 * l);
            #pragma unroll
            for (int i = 0; i < 4; i++) {
                float x = base[i * D + d];
                ax[i] += x * m.x;
                ay[i] += x * m.y;
            }
        }
        #pragma unroll
        for (int i = 0; i < 4; i++) {
            float tx = TEMP * ax[i], ty = TEMP * ay[i];
            float mx = fmaxf(tx, ty);
            #pragma unroll
            for (int o = 16; o > 0; o >>= 1)
                mx = fmaxf(mx, __shfl_xor_sync(0xffffffffu, mx, o));
            float ex = __expf(tx - mx), ey = __expf(ty - mx);
            float s = ex + ey;
            #pragma unroll
            for (int o = 16; o > 0; o >>= 1)
                s += __shfl_xor_sync(0xffffffffu, s, o);
            float invs = 1.0f / s;
            float2 rv = make_float2(ex * invs, ey * invs);
            *(float2*)(sR + (w * 4 + i) * K + 2 * l) = rv;
        }
        __syncthreads();

        if (WRITE_R) {
            float4* dst = (float4*)(r_out + (size_t)c * CHUNK * K);
            #pragma unroll
            for (int i = 0; i < 2; i++)
                dst[tid + 256 * i] = ((const float4*)sR)[tid + 256 * i];
        }

        // ---- phase C: acc[kIdx][dblk*32 + j] += r[n][kIdx] * data[n][...] ----
        const float* dcol = sData + dblk * 32;
        #pragma unroll 4
        for (int n = 0; n < CHUNK; n++) {
            float rv = sR[n * K + kIdx];
            cacc += rv;
            const float4* dp = (const float4*)(dcol + n * D);
            #pragma unroll
            for (int j = 0; j < 8; j++) {
                float4 v = dp[j];
                acc[4 * j + 0] += rv * v.x;
                acc[4 * j + 1] += rv * v.y;
                acc[4 * j + 2] += rv * v.z;
                acc[4 * j + 3] += rv * v.w;
            }
        }
        __syncthreads();
    }

    // flush partials
    float* gm = g_mean + kIdx * D + dblk * 32;
    #pragma unroll
    for (int j = 0; j < 32; j++) atomicAdd(gm + j, acc[j]);
    if (dblk == 0) atomicAdd(&g_cnt[kIdx], cacc);
}

// ---------------------------------------------------------------------------
// mu = mean / cnt; if not last: normalize + transpose into g_muT; zero accs.
// grid=K, block=128.
__global__ void update_kernel(int last, float* __restrict__ mu_out) {
    int k = blockIdx.x;
    int d = threadIdx.x;
    float cnt = g_cnt[k];
    float v = g_mean[k * D + d] / cnt;
    __shared__ float sred[4];
    float ss = v * v;
    #pragma unroll
    for (int o = 16; o > 0; o >>= 1) ss += __shfl_xor_sync(0xffffffffu, ss, o);
    if ((d & 31) == 0) sred[d >> 5] = ss;
    __syncthreads();   // also guarantees g_cnt[k] fully read before zeroing
    float tot = sred[0] + sred[1] + sred[2] + sred[3];
    if (last) {
        mu_out[k * D + d] = v;
    } else {
        g_muT[d * K + k] = v / (sqrtf(tot) + EPSn);
    }
    g_mean[k * D + d] = 0.0f;
    if (d == 0) g_cnt[k] = 0.0f;
}

// ---------------------------------------------------------------------------
extern "C" void kernel_launch(void* const* d_in, const int* in_sizes, int n_in,
                              void* d_out, int out_size) {
    const float* embeds = (const float*)d_in[0];
    const float* init   = (const float*)d_in[1];
    int N = in_sizes[0] / D;
    int nChunks = (N + CHUNK - 1) / CHUNK;
    float* out_mu = (float*)d_out;
    float* out_r  = (float*)d_out + K * D;

    // Opt-in for 56 KB dynamic smem (idempotent; not a stream op).
    cudaFuncSetAttribute(iter_kernel<false>,
                         cudaFuncAttributeMaxDynamicSharedMemorySize, SMEM_BYTES);
    cudaFuncSetAttribute(iter_kernel<true>,
                         cudaFuncAttributeMaxDynamicSharedMemorySize, SMEM_BYTES);

    norm_data_kernel<<<(N + 7) / 8, 256>>>(embeds, N);
    init_mu_kernel<<<K, 128>>>(init);

    for (int it = 0; it < ITERS; it++) {
        int last = (it == ITERS - 1);
        if (last)
            iter_kernel<true><<<296, 256, SMEM_BYTES>>>(out_r, nChunks);
        else
            iter_kernel<false><<<296, 256, SMEM_BYTES>>>(nullptr, nChunks);
        update_kernel<<<K, 128>>>(last, out_mu);
    }
}

// round 3
// speedup vs baseline: 1.2803x; 1.2803x over previous
#include <cuda_runtime.h>

#define D      128
#define K      64
#define N_MAX  200000
#define TEMP   30.0f
#define EPSn   1e-6f
#define CHUNK  64
#define ITERS  11
#define MU_STRIDE 132   // padded row stride for sMu (16B-aligned, bank-spread)

#define SMEM_BYTES ((K*MU_STRIDE + CHUNK*D + CHUNK*D) * 4)

// Scratch (no allocation allowed in kernel_launch)
__device__ float g_dataN[(size_t)N_MAX * D];  // normalized data, PERMUTED cols
__device__ float g_muT[K * D];                // normalized mu, [k][col] PERMUTED
__device__ float g_mean[K * D];               // accumulator, PERMUTED cols
__device__ float g_cnt[K];

// column permutation: real dim d -> col. 4-blocks: even blocks -> 0..15, odd -> 16..31
__host__ __device__ __forceinline__ int perm_col(int d) {
    int B = d >> 2;
    int pb = ((B & 1) << 4) + (B >> 1);
    return (pb << 2) + (d & 3);
}

// packed dual-fp32 FMA (sm_100+/sm_103a): d = a*b + c elementwise on 2 floats
#define FMA2(d_, a_, b_, c_) \
    asm("fma.rn.f32x2 %0, %1, %2, %3;" : "=l"(d_) : "l"(a_), "l"(b_), "l"(c_))

__device__ __forceinline__ float u64lo(unsigned long long v) {
    return __uint_as_float((unsigned)v);
}
__device__ __forceinline__ float u64hi(unsigned long long v) {
    return __uint_as_float((unsigned)(v >> 32));
}

// ---------------------------------------------------------------------------
// One warp per row: normalize data rows once, write col-permuted.
__global__ void norm_data_kernel(const float* __restrict__ x, int N) {
    int w = (blockIdx.x * blockDim.x + threadIdx.x) >> 5;
    int lane = threadIdx.x & 31;
    if (w >= N) return;
    const float4* row = (const float4*)(x + (size_t)w * D);
    float4 v = row[lane];
    float ss = v.x*v.x + v.y*v.y + v.z*v.z + v.w*v.w;
    #pragma unroll
    for (int o = 16; o > 0; o >>= 1) ss += __shfl_xor_sync(0xffffffffu, ss, o);
    float inv = 1.0f / (sqrtf(ss) + EPSn);
    float4 o4 = make_float4(v.x*inv, v.y*inv, v.z*inv, v.w*inv);
    int pb = ((lane & 1) << 4) + (lane >> 1);   // permuted 4-block index
    ((float4*)(g_dataN + (size_t)w * D))[pb] = o4;
}

// ---------------------------------------------------------------------------
// Normalize init mu -> g_muT ([k][col] permuted), zero accumulators. grid=K, block=128.
__global__ void init_mu_kernel(const float* __restrict__ init) {
    int k = blockIdx.x;
    int d = threadIdx.x;
    float v = init[k * D + d];
    __shared__ float sred[4];
    float ss = v * v;
    #pragma unroll
    for (int o = 16; o > 0; o >>= 1) ss += __shfl_xor_sync(0xffffffffu, ss, o);
    if ((d & 31) == 0) sred[d >> 5] = ss;
    __syncthreads();
    float tot = sred[0] + sred[1] + sred[2] + sred[3];
    g_muT[k * D + perm_col(d)] = v / (sqrtf(tot) + EPSn);
    g_mean[k * D + d] = 0.0f;
    if (d == 0) g_cnt[k] = 0.0f;
}

// ---------------------------------------------------------------------------
// Fused iteration with packed f32x2 FMAs throughout.
// block = 256 (8 warps), occupancy 2, CHUNK = 64 rows.
// Phase B: warp w -> rows 8w..8w+7; lane l -> clusters (l, l+32); pack over d-pairs.
// Phase C: thread -> 4 clusters x 8 dims; pack over d-pairs with pre-splatted r.
template<bool WRITE_R>
__global__ void __launch_bounds__(256, 2) iter_kernel(float* __restrict__ r_out,
                                                      int nChunks) {
    extern __shared__ float sm[];
    float* sMu   = sm;                       // [64][132], permuted cols
    float* sData = sm + K * MU_STRIDE;       // [64][128], permuted cols
    float* sRs   = sData + CHUNK * D;        // [64][128]: 64 splat-float2 per row

    int tid = threadIdx.x, w = tid >> 5, l = tid & 31;

    // stage mu (33 KB) with padded rows
    #pragma unroll
    for (int i = tid; i < K * D / 4; i += 256) {
        int k = i >> 5, c4 = i & 31;
        *(float4*)(sMu + k * MU_STRIDE + c4 * 4) = ((const float4*)g_muT)[i];
    }

    // phase-C tile ownership: 16 kgrps x 16 dblks = 256 threads
    int kgrp = (l & 3) + ((w & 3) << 2);
    int dblk = (l >> 2) + ((w >> 2) << 3);
    int k0 = kgrp * 4, d0 = dblk * 8;
    unsigned long long accC[4][4];
    #pragma unroll
    for (int a = 0; a < 4; a++)
        #pragma unroll
        for (int b = 0; b < 4; b++) accC[a][b] = 0ULL;
    float s0 = 0.0f, s1 = 0.0f;   // cluster_r partials for clusters l, l+32

    __syncthreads();

    for (int c = blockIdx.x; c < nChunks; c += gridDim.x) {
        // ---- phase A: stage 64 rows (32 KB), layout already permuted ----
        const float4* src = (const float4*)(g_dataN + (size_t)c * CHUNK * D);
        #pragma unroll
        for (int i = 0; i < 8; i++)
            ((float4*)sData)[tid + 256 * i] = src[tid + 256 * i];
        __syncthreads();

        // ---- phase B: dist via FMA2, packed over d-pairs ----
        unsigned long long a0[8], a1[8];
        #pragma unroll
        for (int r = 0; r < 8; r++) { a0[r] = 0ULL; a1[r] = 0ULL; }
        const float* xbase  = sData + (w * 8) * D;
        const float* m0base = sMu + l * MU_STRIDE;
        const float* m1base = sMu + (l + 32) * MU_STRIDE;
        #pragma unroll 4
        for (int col = 0; col < D; col += 4) {
            ulonglong2 m0 = *(const ulonglong2*)(m0base + col);
            ulonglong2 m1 = *(const ulonglong2*)(m1base + col);
            #pragma unroll
            for (int r = 0; r < 8; r++) {
                ulonglong2 xv = *(const ulonglong2*)(xbase + r * D + col);
                FMA2(a0[r], xv.x, m0.x, a0[r]);
                FMA2(a0[r], xv.y, m0.y, a0[r]);
                FMA2(a1[r], xv.x, m1.x, a1[r]);
                FMA2(a1[r], xv.y, m1.y, a1[r]);
            }
        }

        // ---- softmax (per row, warp-wide over 64 clusters) ----
        #pragma unroll
        for (int r = 0; r < 8; r++) {
            float tx = TEMP * (u64lo(a0[r]) + u64hi(a0[r]));
            float ty = TEMP * (u64lo(a1[r]) + u64hi(a1[r]));
            float mx = fmaxf(tx, ty);
            #pragma unroll
            for (int o = 16; o > 0; o >>= 1)
                mx = fmaxf(mx, __shfl_xor_sync(0xffffffffu, mx, o));
            float ex = __expf(tx - mx), ey = __expf(ty - mx);
            float s = ex + ey;
            #pragma unroll
            for (int o = 16; o > 0; o >>= 1)
                s += __shfl_xor_sync(0xffffffffu, s, o);
            float inv = __fdividef(1.0f, s);
            float rx = ex * inv, ry = ey * inv;
            s0 += rx; s1 += ry;
            int row = w * 8 + r;
            *(float2*)(sRs + row * D + 2 * l)        = make_float2(rx, rx);
            *(float2*)(sRs + row * D + 2 * (l + 32)) = make_float2(ry, ry);
            if (WRITE_R) {
                float* ro = r_out + ((size_t)c * CHUNK + row) * K;
                ro[l]      = rx;
                ro[l + 32] = ry;
            }
        }
        __syncthreads();

        // ---- phase C: accC[k][dpair] += splat(r) * x, FMA2 ----
        #pragma unroll 4
        for (int n = 0; n < CHUNK; n++) {
            ulonglong2 x01 = *(const ulonglong2*)(sData + n * D + d0);
            ulonglong2 x23 = *(const ulonglong2*)(sData + n * D + d0 + 4);
            ulonglong2 r01 = *(const ulonglong2*)(sRs + n * D + 2 * k0);
            ulonglong2 r23 = *(const ulonglong2*)(sRs + n * D + 2 * k0 + 4);
            FMA2(accC[0][0], x01.x, r01.x, accC[0][0]);
            FMA2(accC[0][1], x01.y, r01.x, accC[0][1]);
            FMA2(accC[0][2], x23.x, r01.x, accC[0][2]);
            FMA2(accC[0][3], x23.y, r01.x, accC[0][3]);
            FMA2(accC[1][0], x01.x, r01.y, accC[1][0]);
            FMA2(accC[1][1], x01.y, r01.y, accC[1][1]);
            FMA2(accC[1][2], x23.x, r01.y, accC[1][2]);
            FMA2(accC[1][3], x23.y, r01.y, accC[1][3]);
            FMA2(accC[2][0], x01.x, r23.x, accC[2][0]);
            FMA2(accC[2][1], x01.y, r23.x, accC[2][1]);
            FMA2(accC[2][2], x23.x, r23.x, accC[2][2]);
            FMA2(accC[2][3], x23.y, r23.x, accC[2][3]);
            FMA2(accC[3][0], x01.x, r23.y, accC[3][0]);
            FMA2(accC[3][1], x01.y, r23.y, accC[3][1]);
            FMA2(accC[3][2], x23.x, r23.y, accC[3][2]);
            FMA2(accC[3][3], x23.y, r23.y, accC[3][3]);
        }
        __syncthreads();
    }

    // flush partials (g_mean is in permuted col layout)
    #pragma unroll
    for (int kk = 0; kk < 4; kk++)
        #pragma unroll
        for (int dp = 0; dp < 4; dp++) {
            atomicAdd(&g_mean[(k0 + kk) * D + d0 + 2 * dp],     u64lo(accC[kk][dp]));
            atomicAdd(&g_mean[(k0 + kk) * D + d0 + 2 * dp + 1], u64hi(accC[kk][dp]));
        }
    atomicAdd(&g_cnt[l],      s0);
    atomicAdd(&g_cnt[l + 32], s1);
}

// ---------------------------------------------------------------------------
// mu = mean / cnt; if not last: normalize into g_muT (permuted); zero accs.
// grid=K, block=128. mu_out written in REAL layout.
__global__ void update_kernel(int last, float* __restrict__ mu_out) {
    int k = blockIdx.x;
    int d = threadIdx.x;
    int col = perm_col(d);
    float cnt = g_cnt[k];
    float v = g_mean[k * D + col] / cnt;
    __shared__ float sred[4];
    float ss = v * v;
    #pragma unroll
    for (int o = 16; o > 0; o >>= 1) ss += __shfl_xor_sync(0xffffffffu, ss, o);
    if ((d & 31) == 0) sred[d >> 5] = ss;
    __syncthreads();   // also guarantees g_cnt[k] fully read before zeroing
    float tot = sred[0] + sred[1] + sred[2] + sred[3];
    if (last) {
        mu_out[k * D + d] = v;
    } else {
        g_muT[k * D + col] = v / (sqrtf(tot) + EPSn);
    }
    g_mean[k * D + col] = 0.0f;
    if (d == 0) g_cnt[k] = 0.0f;
}

// ---------------------------------------------------------------------------
extern "C" void kernel_launch(void* const* d_in, const int* in_sizes, int n_in,
                              void* d_out, int out_size) {
    const float* embeds = (const float*)d_in[0];
    const float* init   = (const float*)d_in[1];
    int N = in_sizes[0] / D;
    int nChunks = (N + CHUNK - 1) / CHUNK;   // N=200000 -> 3125 exact
    float* out_mu = (float*)d_out;
    float* out_r  = (float*)d_out + K * D;

    cudaFuncSetAttribute(iter_kernel<false>,
                         cudaFuncAttributeMaxDynamicSharedMemorySize, SMEM_BYTES);
    cudaFuncSetAttribute(iter_kernel<true>,
                         cudaFuncAttributeMaxDynamicSharedMemorySize, SMEM_BYTES);

    norm_data_kernel<<<(N + 7) / 8, 256>>>(embeds, N);
    init_mu_kernel<<<K, 128>>>(init);

    for (int it = 0; it < ITERS; it++) {
        int last = (it == ITERS - 1);
        if (last)
            iter_kernel<true><<<296, 256, SMEM_BYTES>>>(out_r, nChunks);
        else
            iter_kernel<false><<<296, 256, SMEM_BYTES>>>(nullptr, nChunks);
        update_kernel<<<K, 128>>>(last, out_mu);
    }
}

// round 4
// speedup vs baseline: 1.2804x; 1.0000x over previous
#include <cuda_runtime.h>

#define D      128
#define K      64
#define N_MAX  200000
#define TEMP   30.0f
#define EPSn   1e-6f
#define CHUNK  64
#define ITERS  11
#define MU_STRIDE 132   // padded row stride for sMu (16B-aligned, bank-spread)

#define SMEM_BYTES ((K*MU_STRIDE + CHUNK*D + CHUNK*D) * 4)

// Scratch (no allocation allowed in kernel_launch)
__device__ float g_dataN[(size_t)N_MAX * D];  // normalized data, PERMUTED cols
__device__ float g_muT[K * D];                // normalized mu, [k][col] PERMUTED
__device__ float g_mean[K * D];               // accumulator, PERMUTED cols
__device__ float g_cnt[K];

// column permutation: real dim d -> col. 4-blocks: even blocks -> 0..15, odd -> 16..31
__host__ __device__ __forceinline__ int perm_col(int d) {
    int B = d >> 2;
    int pb = ((B & 1) << 4) + (B >> 1);
    return (pb << 2) + (d & 3);
}

// packed dual-fp32 FMA (sm_100+/sm_103a): d = a*b + c elementwise on 2 floats
#define FMA2(d_, a_, b_, c_) \
    asm("fma.rn.f32x2 %0, %1, %2, %3;" : "=l"(d_) : "l"(a_), "l"(b_), "l"(c_))

__device__ __forceinline__ float u64lo(unsigned long long v) {
    return __uint_as_float((unsigned)v);
}
__device__ __forceinline__ float u64hi(unsigned long long v) {
    return __uint_as_float((unsigned)(v >> 32));
}

// ---------------------------------------------------------------------------
// One warp per row: normalize data rows once, write col-permuted.
__global__ void norm_data_kernel(const float* __restrict__ x, int N) {
    int w = (blockIdx.x * blockDim.x + threadIdx.x) >> 5;
    int lane = threadIdx.x & 31;
    if (w >= N) return;
    const float4* row = (const float4*)(x + (size_t)w * D);
    float4 v = row[lane];
    float ss = v.x*v.x + v.y*v.y + v.z*v.z + v.w*v.w;
    #pragma unroll
    for (int o = 16; o > 0; o >>= 1) ss += __shfl_xor_sync(0xffffffffu, ss, o);
    float inv = 1.0f / (sqrtf(ss) + EPSn);
    float4 o4 = make_float4(v.x*inv, v.y*inv, v.z*inv, v.w*inv);
    int pb = ((lane & 1) << 4) + (lane >> 1);   // permuted 4-block index
    ((float4*)(g_dataN + (size_t)w * D))[pb] = o4;
}

// ---------------------------------------------------------------------------
// Normalize init mu -> g_muT ([k][col] permuted), zero accumulators. grid=K, block=128.
__global__ void init_mu_kernel(const float* __restrict__ init) {
    int k = blockIdx.x;
    int d = threadIdx.x;
    float v = init[k * D + d];
    __shared__ float sred[4];
    float ss = v * v;
    #pragma unroll
    for (int o = 16; o > 0; o >>= 1) ss += __shfl_xor_sync(0xffffffffu, ss, o);
    if ((d & 31) == 0) sred[d >> 5] = ss;
    __syncthreads();
    float tot = sred[0] + sred[1] + sred[2] + sred[3];
    g_muT[k * D + perm_col(d)] = v / (sqrtf(tot) + EPSn);
    g_mean[k * D + d] = 0.0f;
    if (d == 0) g_cnt[k] = 0.0f;
}

// ---------------------------------------------------------------------------
// Fused iteration with packed f32x2 FMAs throughout.
// block = 256 (8 warps), occupancy 2, CHUNK = 64 rows.
// Phase B: warp w -> rows 8w..8w+7; lane l -> clusters (l, l+32); pack over d-pairs.
// Phase C: thread -> 4 clusters x 8 dims; pack over d-pairs with pre-splatted r.
template<bool WRITE_R>
__global__ void __launch_bounds__(256, 2) iter_kernel(float* __restrict__ r_out,
                                                      int nChunks) {
    extern __shared__ float sm[];
    float* sMu   = sm;                       // [64][132], permuted cols
    float* sData = sm + K * MU_STRIDE;       // [64][128], permuted cols
    float* sRs   = sData + CHUNK * D;        // [64][128]: 64 splat-float2 per row

    int tid = threadIdx.x, w = tid >> 5, l = tid & 31;

    // stage mu (33 KB) with padded rows
    #pragma unroll
    for (int i = tid; i < K * D / 4; i += 256) {
        int k = i >> 5, c4 = i & 31;
        *(float4*)(sMu + k * MU_STRIDE + c4 * 4) = ((const float4*)g_muT)[i];
    }

    // phase-C tile ownership: 16 kgrps x 16 dblks = 256 threads
    int kgrp = (l & 3) + ((w & 3) << 2);
    int dblk = (l >> 2) + ((w >> 2) << 3);
    int k0 = kgrp * 4, d0 = dblk * 8;
    unsigned long long accC[4][4];
    #pragma unroll
    for (int a = 0; a < 4; a++)
        #pragma unroll
        for (int b = 0; b < 4; b++) accC[a][b] = 0ULL;
    float s0 = 0.0f, s1 = 0.0f;   // cluster_r partials for clusters l, l+32

    __syncthreads();

    for (int c = blockIdx.x; c < nChunks; c += gridDim.x) {
        // ---- phase A: stage 64 rows (32 KB), layout already permuted ----
        const float4* src = (const float4*)(g_dataN + (size_t)c * CHUNK * D);
        #pragma unroll
        for (int i = 0; i < 8; i++)
            ((float4*)sData)[tid + 256 * i] = src[tid + 256 * i];
        __syncthreads();

        // ---- phase B: dist via FMA2, packed over d-pairs ----
        unsigned long long a0[8], a1[8];
        #pragma unroll
        for (int r = 0; r < 8; r++) { a0[r] = 0ULL; a1[r] = 0ULL; }
        const float* xbase  = sData + (w * 8) * D;
        const float* m0base = sMu + l * MU_STRIDE;
        const float* m1base = sMu + (l + 32) * MU_STRIDE;
        #pragma unroll 4
        for (int col = 0; col < D; col += 4) {
            ulonglong2 m0 = *(const ulonglong2*)(m0base + col);
            ulonglong2 m1 = *(const ulonglong2*)(m1base + col);
            #pragma unroll
            for (int r = 0; r < 8; r++) {
                ulonglong2 xv = *(const ulonglong2*)(xbase + r * D + col);
                FMA2(a0[r], xv.x, m0.x, a0[r]);
                FMA2(a0[r], xv.y, m0.y, a0[r]);
                FMA2(a1[r], xv.x, m1.x, a1[r]);
                FMA2(a1[r], xv.y, m1.y, a1[r]);
            }
        }

        // ---- softmax (per row, warp-wide over 64 clusters) ----
        #pragma unroll
        for (int r = 0; r < 8; r++) {
            float tx = TEMP * (u64lo(a0[r]) + u64hi(a0[r]));
            float ty = TEMP * (u64lo(a1[r]) + u64hi(a1[r]));
            float mx = fmaxf(tx, ty);
            #pragma unroll
            for (int o = 16; o > 0; o >>= 1)
                mx = fmaxf(mx, __shfl_xor_sync(0xffffffffu, mx, o));
            float ex = __expf(tx - mx), ey = __expf(ty - mx);
            float s = ex + ey;
            #pragma unroll
            for (int o = 16; o > 0; o >>= 1)
                s += __shfl_xor_sync(0xffffffffu, s, o);
            float inv = __fdividef(1.0f, s);
            float rx = ex * inv, ry = ey * inv;
            s0 += rx; s1 += ry;
            int row = w * 8 + r;
            *(float2*)(sRs + row * D + 2 * l)        = make_float2(rx, rx);
            *(float2*)(sRs + row * D + 2 * (l + 32)) = make_float2(ry, ry);
            if (WRITE_R) {
                float* ro = r_out + ((size_t)c * CHUNK + row) * K;
                ro[l]      = rx;
                ro[l + 32] = ry;
            }
        }
        __syncthreads();

        // ---- phase C: accC[k][dpair] += splat(r) * x, FMA2 ----
        #pragma unroll 4
        for (int n = 0; n < CHUNK; n++) {
            ulonglong2 x01 = *(const ulonglong2*)(sData + n * D + d0);
            ulonglong2 x23 = *(const ulonglong2*)(sData + n * D + d0 + 4);
            ulonglong2 r01 = *(const ulonglong2*)(sRs + n * D + 2 * k0);
            ulonglong2 r23 = *(const ulonglong2*)(sRs + n * D + 2 * k0 + 4);
            FMA2(accC[0][0], x01.x, r01.x, accC[0][0]);
            FMA2(accC[0][1], x01.y, r01.x, accC[0][1]);
            FMA2(accC[0][2], x23.x, r01.x, accC[0][2]);
            FMA2(accC[0][3], x23.y, r01.x, accC[0][3]);
            FMA2(accC[1][0], x01.x, r01.y, accC[1][0]);
            FMA2(accC[1][1], x01.y, r01.y, accC[1][1]);
            FMA2(accC[1][2], x23.x, r01.y, accC[1][2]);
            FMA2(accC[1][3], x23.y, r01.y, accC[1][3]);
            FMA2(accC[2][0], x01.x, r23.x, accC[2][0]);
            FMA2(accC[2][1], x01.y, r23.x, accC[2][1]);
            FMA2(accC[2][2], x23.x, r23.x, accC[2][2]);
            FMA2(accC[2][3], x23.y, r23.x, accC[2][3]);
            FMA2(accC[3][0], x01.x, r23.y, accC[3][0]);
            FMA2(accC[3][1], x01.y, r23.y, accC[3][1]);
            FMA2(accC[3][2], x23.x, r23.y, accC[3][2]);
            FMA2(accC[3][3], x23.y, r23.y, accC[3][3]);
        }
        __syncthreads();
    }

    // flush partials (g_mean is in permuted col layout)
    #pragma unroll
    for (int kk = 0; kk < 4; kk++)
        #pragma unroll
        for (int dp = 0; dp < 4; dp++) {
            atomicAdd(&g_mean[(k0 + kk) * D + d0 + 2 * dp],     u64lo(accC[kk][dp]));
            atomicAdd(&g_mean[(k0 + kk) * D + d0 + 2 * dp + 1], u64hi(accC[kk][dp]));
        }
    atomicAdd(&g_cnt[l],      s0);
    atomicAdd(&g_cnt[l + 32], s1);
}

// ---------------------------------------------------------------------------
// mu = mean / cnt; if not last: normalize into g_muT (permuted); zero accs.
// grid=K, block=128. mu_out written in REAL layout.
__global__ void update_kernel(int last, float* __restrict__ mu_out) {
    int k = blockIdx.x;
    int d = threadIdx.x;
    int col = perm_col(d);
    float cnt = g_cnt[k];
    float v = g_mean[k * D + col] / cnt;
    __shared__ float sred[4];
    float ss = v * v;
    #pragma unroll
    for (int o = 16; o > 0; o >>= 1) ss += __shfl_xor_sync(0xffffffffu, ss, o);
    if ((d & 31) == 0) sred[d >> 5] = ss;
    __syncthreads();   // also guarantees g_cnt[k] fully read before zeroing
    float tot = sred[0] + sred[1] + sred[2] + sred[3];
    if (last) {
        mu_out[k * D + d] = v;
    } else {
        g_muT[k * D + col] = v / (sqrtf(tot) + EPSn);
    }
    g_mean[k * D + col] = 0.0f;
    if (d == 0) g_cnt[k] = 0.0f;
}

// ---------------------------------------------------------------------------
extern "C" void kernel_launch(void* const* d_in, const int* in_sizes, int n_in,
                              void* d_out, int out_size) {
    const float* embeds = (const float*)d_in[0];
    const float* init   = (const float*)d_in[1];
    int N = in_sizes[0] / D;
    int nChunks = (N + CHUNK - 1) / CHUNK;   // N=200000 -> 3125 exact
    float* out_mu = (float*)d_out;
    float* out_r  = (float*)d_out + K * D;

    cudaFuncSetAttribute(iter_kernel<false>,
                         cudaFuncAttributeMaxDynamicSharedMemorySize, SMEM_BYTES);
    cudaFuncSetAttribute(iter_kernel<true>,
                         cudaFuncAttributeMaxDynamicSharedMemorySize, SMEM_BYTES);

    norm_data_kernel<<<(N + 7) / 8, 256>>>(embeds, N);
    init_mu_kernel<<<K, 128>>>(init);

    for (int it = 0; it < ITERS; it++) {
        int last = (it == ITERS - 1);
        if (last)
            iter_kernel<true><<<296, 256, SMEM_BYTES>>>(out_r, nChunks);
        else
            iter_kernel<false><<<296, 256, SMEM_BYTES>>>(nullptr, nChunks);
        update_kernel<<<K, 128>>>(last, out_mu);
    }
}

// round 6
// speedup vs baseline: 3.5867x; 2.8013x over previous
#include <cuda_runtime.h>
#include <cuda_bf16.h>
#include <cstdint>

#define D 128
#define K 64
#define TILE 128
#define NT_MAX 1563
#define NB 148
#define TEMP 30.0f
#define EPSn 1e-6f
#define ITERS 11

// smem byte offsets
#define OFF_MU 0                 // MuH 16KB | MuL 16KB
#define OFF_X  32768             // buf0: Xh 32K | Xl 32K ; buf1 at +65536
#define OFF_R  163840            // Rh 16K | Rl 16K
#define OFF_CNT 196608           // 8*64 floats
#define SMEM_TOTAL (OFF_CNT + 2048)

__device__ __align__(16) unsigned char g_x[(size_t)NT_MAX * 65536]; // per tile: Xh 32K | Xl 32K, swizzled
__device__ __align__(16) unsigned char g_mu[32768];                 // MuH 16K | MuL 16K, swizzled
__device__ float g_pmean[NB * K * D];
__device__ float g_pcnt[NB * K];

__device__ __forceinline__ uint32_t smem_u32(const void* p) {
    uint32_t a;
    asm("{ .reg .u64 t; cvta.to.shared.u64 t, %1; cvt.u32.u64 %0, t; }" : "=r"(a) : "l"(p));
    return a;
}
__device__ __forceinline__ void ldsm_x4(uint32_t* r, uint32_t a) {
    asm volatile("ldmatrix.sync.aligned.m8n8.x4.shared.b16 {%0,%1,%2,%3}, [%4];"
        : "=r"(r[0]), "=r"(r[1]), "=r"(r[2]), "=r"(r[3]) : "r"(a));
}
__device__ __forceinline__ void ldsm_x4t(uint32_t* r, uint32_t a) {
    asm volatile("ldmatrix.sync.aligned.m8n8.x4.trans.shared.b16 {%0,%1,%2,%3}, [%4];"
        : "=r"(r[0]), "=r"(r[1]), "=r"(r[2]), "=r"(r[3]) : "r"(a));
}
__device__ __forceinline__ void ldsm_x2(uint32_t* r, uint32_t a) {
    asm volatile("ldmatrix.sync.aligned.m8n8.x2.shared.b16 {%0,%1}, [%2];"
        : "=r"(r[0]), "=r"(r[1]) : "r"(a));
}
__device__ __forceinline__ void ldsm_x2t(uint32_t* r, uint32_t a) {
    asm volatile("ldmatrix.sync.aligned.m8n8.x2.trans.shared.b16 {%0,%1}, [%2];"
        : "=r"(r[0]), "=r"(r[1]) : "r"(a));
}
__device__ __forceinline__ void mma_bf16(float* c, const uint32_t* a, const uint32_t* b) {
    asm volatile("mma.sync.aligned.m16n8k16.row.col.f32.bf16.bf16.f32 "
        "{%0,%1,%2,%3}, {%4,%5,%6,%7}, {%8,%9}, {%0,%1,%2,%3};"
        : "+f"(c[0]), "+f"(c[1]), "+f"(c[2]), "+f"(c[3])
        : "r"(a[0]), "r"(a[1]), "r"(a[2]), "r"(a[3]), "r"(b[0]), "r"(b[1]));
}
__device__ __forceinline__ void cp16(uint32_t dst, const void* src) {
    asm volatile("cp.async.cg.shared.global [%0], [%1], 16;" :: "r"(dst), "l"(src) : "memory");
}
#define CP_COMMIT() asm volatile("cp.async.commit_group;" ::: "memory")
#define CP_WAIT0()  asm volatile("cp.async.wait_group 0;" ::: "memory")

__device__ __forceinline__ uint32_t pack_bf16x2(__nv_bfloat16 a, __nv_bfloat16 b) {
    __nv_bfloat162 v(a, b);
    return *(uint32_t*)&v;
}

// ---------------------------------------------------------------------------
// prep: normalize rows, split fp32->bf16 hi/lo, write swizzled tiles (pad rows zero)
__global__ void prep_kernel(const float* __restrict__ x, int N, int rowsPad) {
    int w = (blockIdx.x * blockDim.x + threadIdx.x) >> 5;
    int lane = threadIdx.x & 31;
    if (w >= rowsPad) return;
    float4 v = make_float4(0.f, 0.f, 0.f, 0.f);
    if (w < N) {
        v = ((const float4*)(x + (size_t)w * D))[lane];
        float ss = v.x*v.x + v.y*v.y + v.z*v.z + v.w*v.w;
        #pragma unroll
        for (int o = 16; o > 0; o >>= 1) ss += __shfl_xor_sync(0xffffffffu, ss, o);
        float inv = 1.0f / (sqrtf(ss) + EPSn);
        v.x *= inv; v.y *= inv; v.z *= inv; v.w *= inv;
    }
    float f[4] = {v.x, v.y, v.z, v.w};
    __nv_bfloat16 h[4], lo[4];
    #pragma unroll
    for (int i = 0; i < 4; i++) {
        h[i]  = __float2bfloat16(f[i]);
        lo[i] = __float2bfloat16(f[i] - __bfloat162float(h[i]));
    }
    uint2 uh, ul;
    uh.x = pack_bf16x2(h[0], h[1]);  uh.y = pack_bf16x2(h[2], h[3]);
    ul.x = pack_bf16x2(lo[0], lo[1]); ul.y = pack_bf16x2(lo[2], lo[3]);
    int t = w >> 7, rl = w & 127, d0 = lane * 4;
    uint32_t off = (uint32_t)rl * 256 + ((((d0 >> 3) ^ (rl & 7)) & 15) << 4) + ((d0 & 7) << 1);
    unsigned char* base = g_x + (size_t)t * 65536;
    *(uint2*)(base + off)         = uh;
    *(uint2*)(base + 32768 + off) = ul;
}

// ---------------------------------------------------------------------------
__device__ __forceinline__ void write_mu(int k, int d, float nv) {
    __nv_bfloat16 h = __float2bfloat16(nv);
    __nv_bfloat16 l = __float2bfloat16(nv - __bfloat162float(h));
    uint32_t off = (uint32_t)k * 256 + ((((d >> 3) ^ (k & 7)) & 15) << 4) + ((d & 7) << 1);
    *(__nv_bfloat16*)(g_mu + off)         = h;
    *(__nv_bfloat16*)(g_mu + 16384 + off) = l;
}

__global__ void init_mu_kernel(const float* __restrict__ init) {
    int k = blockIdx.x, d = threadIdx.x;
    float v = init[k * D + d];
    __shared__ float sred[4];
    float ss = v * v;
    #pragma unroll
    for (int o = 16; o > 0; o >>= 1) ss += __shfl_xor_sync(0xffffffffu, ss, o);
    if ((d & 31) == 0) sred[d >> 5] = ss;
    __syncthreads();
    float tot = sred[0] + sred[1] + sred[2] + sred[3];
    write_mu(k, d, v / (sqrtf(tot) + EPSn));
}

__global__ void update_kernel(int last, float* __restrict__ mu_out) {
    int k = blockIdx.x, d = threadIdx.x;
    float sum = 0.0f, cs = 0.0f;
    #pragma unroll 4
    for (int b = 0; b < NB; b++) {
        sum += g_pmean[b * (K * D) + k * D + d];
        cs  += g_pcnt[b * K + k];
    }
    float v = sum / cs;
    __shared__ float sred[4];
    float ss = v * v;
    #pragma unroll
    for (int o = 16; o > 0; o >>= 1) ss += __shfl_xor_sync(0xffffffffu, ss, o);
    if ((d & 31) == 0) sred[d >> 5] = ss;
    __syncthreads();
    float tot = sred[0] + sred[1] + sred[2] + sred[3];
    if (last) mu_out[k * D + d] = v;
    else      write_mu(k, d, v / (sqrtf(tot) + EPSn));
}

// ---------------------------------------------------------------------------
template<bool LAST>
__global__ void __launch_bounds__(256, 1) iter_kernel(float* __restrict__ r_out,
                                                      int N, int nT) {
    extern __shared__ unsigned char sm[];
    int tid = threadIdx.x, w = tid >> 5, lane = tid & 31;
    int bid = blockIdx.x;
    int t0 = (int)((long long)bid * nT / gridDim.x);
    int t1 = (int)((long long)(bid + 1) * nT / gridDim.x);
    float* gp = g_pmean + (size_t)bid * K * D;
    if (t0 >= t1) {
        for (int i = tid; i < K * D; i += 256) gp[i] = 0.0f;
        if (tid < K) g_pcnt[bid * K + tid] = 0.0f;
        return;
    }
    uint32_t sb = smem_u32(sm);
    uint32_t sMuH = sb + OFF_MU;
    uint32_t sR   = sb + OFF_R;
    float* scnt = (float*)(sm + OFF_CNT);

    // stage Mu (32KB) + X(t0) (64KB)
    #pragma unroll
    for (int j = 0; j < 8; j++)
        cp16(sMuH + (tid + 256 * j) * 16, g_mu + (tid + 256 * j) * 16);
    {
        const unsigned char* gx = g_x + (size_t)t0 * 65536;
        #pragma unroll
        for (int j = 0; j < 16; j++)
            cp16(sb + OFF_X + (tid + 256 * j) * 16, gx + (tid + 256 * j) * 16);
    }
    CP_COMMIT(); CP_WAIT0();
    __syncthreads();

    float C2[8][4];
    #pragma unroll
    for (int f = 0; f < 8; f++)
        #pragma unroll
        for (int q = 0; q < 4; q++) C2[f][q] = 0.0f;
    float cacc[16];
    #pragma unroll
    for (int j = 0; j < 16; j++) cacc[j] = 0.0f;

    int m0  = w * 16;                       // GEMM1 row strip
    int kc0 = (w & 3) * 16;                 // GEMM2 cluster strip
    int db  = (w >> 2) * 64;                // GEMM2 d half
    int g = lane >> 2, j2 = lane & 3;

    for (int t = t0; t < t1; t++) {
        int buf = (t - t0) & 1;
        uint32_t sX = sb + OFF_X + buf * 65536;       // Xh; Xl at +32768
        if (t + 1 < t1) {
            const unsigned char* gx = g_x + (size_t)(t + 1) * 65536;
            uint32_t dst = sb + OFF_X + (buf ^ 1) * 65536;
            #pragma unroll
            for (int j = 0; j < 16; j++)
                cp16(dst + (tid + 256 * j) * 16, gx + (tid + 256 * j) * 16);
        }
        CP_COMMIT();

        // ---- GEMM1: C1[16 rows x 64 kc] = X . Mu^T (3-term split) ----
        float C1[8][4];
        #pragma unroll
        for (int f = 0; f < 8; f++)
            #pragma unroll
            for (int q = 0; q < 4; q++) C1[f][q] = 0.0f;
        #pragma unroll
        for (int ks = 0; ks < 8; ks++) {
            uint32_t ah[4], al[4];
            int ar = m0 + (lane & 15);
            int ac = ks * 16 + ((lane >> 4) << 3);
            uint32_t aaddr = sX + (uint32_t)ar * 256 + ((((ac >> 3) ^ (ar & 7)) & 15) << 4);
            ldsm_x4(ah, aaddr);
            ldsm_x4(al, aaddr + 32768);
            int bc = ks * 16 + ((lane >> 3) & 1) * 8;
            #pragma unroll
            for (int f = 0; f < 8; f++) {
                int brow = 8 * f + (lane & 7);
                uint32_t baddr = sMuH + (uint32_t)brow * 256 + ((((bc >> 3) ^ (brow & 7)) & 15) << 4);
                uint32_t bh[2], bl2[2];
                ldsm_x2(bh, baddr);
                ldsm_x2(bl2, baddr + 16384);
                mma_bf16(C1[f], ah, bh);
                mma_bf16(C1[f], al, bh);
                mma_bf16(C1[f], ah, bl2);
            }
        }

        // ---- softmax (max-free; |logit| <= ~30) ----
        int grow0 = t * TILE + m0 + g;
        int grow1 = grow0 + 8;
        float s0 = 0.0f, s1 = 0.0f;
        #pragma unroll
        for (int f = 0; f < 8; f++) {
            #pragma unroll
            for (int q = 0; q < 4; q++) C1[f][q] = __expf(TEMP * C1[f][q]);
            s0 += C1[f][0] + C1[f][1];
            s1 += C1[f][2] + C1[f][3];
        }
        s0 += __shfl_xor_sync(0xffffffffu, s0, 1); s0 += __shfl_xor_sync(0xffffffffu, s0, 2);
        s1 += __shfl_xor_sync(0xffffffffu, s1, 1); s1 += __shfl_xor_sync(0xffffffffu, s1, 2);
        float inv0 = (grow0 < N) ? 1.0f / s0 : 0.0f;
        float inv1 = (grow1 < N) ? 1.0f / s1 : 0.0f;
        int row0 = m0 + g, row1 = row0 + 8;
        #pragma unroll
        for (int f = 0; f < 8; f++) {
            float r0a = C1[f][0] * inv0, r0b = C1[f][1] * inv0;
            float r1a = C1[f][2] * inv1, r1b = C1[f][3] * inv1;
            cacc[2*f]   += r0a + r1a;
            cacc[2*f+1] += r0b + r1b;
            int kc = 8 * f + 2 * j2;
            // row0 writes
            {
                __nv_bfloat16 ha = __float2bfloat16(r0a), hb = __float2bfloat16(r0b);
                __nv_bfloat16 la = __float2bfloat16(r0a - __bfloat162float(ha));
                __nv_bfloat16 lb = __float2bfloat16(r0b - __bfloat162float(hb));
                uint32_t off = (uint32_t)row0 * 128 + (((f ^ (row0 & 7)) & 7) << 4) + (j2 << 2);
                *(uint32_t*)(sm + OFF_R + off)         = pack_bf16x2(ha, hb);
                *(uint32_t*)(sm + OFF_R + 16384 + off) = pack_bf16x2(la, lb);
            }
            // row1 writes
            {
                __nv_bfloat16 ha = __float2bfloat16(r1a), hb = __float2bfloat16(r1b);
                __nv_bfloat16 la = __float2bfloat16(r1a - __bfloat162float(ha));
                __nv_bfloat16 lb = __float2bfloat16(r1b - __bfloat162float(hb));
                uint32_t off = (uint32_t)row1 * 128 + (((f ^ (row1 & 7)) & 7) << 4) + (j2 << 2);
                *(uint32_t*)(sm + OFF_R + off)         = pack_bf16x2(ha, hb);
                *(uint32_t*)(sm + OFF_R + 16384 + off) = pack_bf16x2(la, lb);
            }
            if (LAST) {
                if (grow0 < N) *(float2*)(r_out + (size_t)grow0 * K + kc) = make_float2(r0a, r0b);
                if (grow1 < N) *(float2*)(r_out + (size_t)grow1 * K + kc) = make_float2(r1a, r1b);
            }
        }
        __syncthreads();

        // ---- GEMM2: C2[16 kc x 64 d] += R^T . X (3-term split) ----
        #pragma unroll
        for (int ks = 0; ks < 8; ks++) {
            int row0k = ks * 16;
            uint32_t ah[4], al[4];
            int arm = row0k + (lane & 7) + ((lane >> 4) << 3);
            int acm = kc0 + ((lane >> 3) & 1) * 8;
            uint32_t aaddr = sR + (uint32_t)arm * 128 + ((((acm >> 3) ^ (arm & 7)) & 7) << 4);
            ldsm_x4t(ah, aaddr);
            ldsm_x4t(al, aaddr + 16384);
            int brm = row0k + (lane & 15);
            #pragma unroll
            for (int f = 0; f < 8; f++) {
                int d0 = db + 8 * f;
                uint32_t baddr = sX + (uint32_t)brm * 256 + ((((d0 >> 3) ^ (brm & 7)) & 15) << 4);
                uint32_t bh[2], bl2[2];
                ldsm_x2t(bh, baddr);
                ldsm_x2t(bl2, baddr + 32768);
                mma_bf16(C2[f], ah, bh);   // Rh . Xh
                mma_bf16(C2[f], al, bh);   // Rl . Xh
                mma_bf16(C2[f], ah, bl2);  // Rh . Xl
            }
        }
        CP_WAIT0();
        __syncthreads();
    }

    // ---- epilogue: counts ----
    #pragma unroll
    for (int j = 0; j < 16; j++) {
        cacc[j] += __shfl_xor_sync(0xffffffffu, cacc[j], 4);
        cacc[j] += __shfl_xor_sync(0xffffffffu, cacc[j], 8);
        cacc[j] += __shfl_xor_sync(0xffffffffu, cacc[j], 16);
    }
    if (lane < 4) {
        #pragma unroll
        for (int f = 0; f < 8; f++) {
            scnt[w * 64 + 8 * f + 2 * lane]     = cacc[2*f];
            scnt[w * 64 + 8 * f + 2 * lane + 1] = cacc[2*f+1];
        }
    }
    __syncthreads();
    if (tid < K) {
        float c = 0.0f;
        #pragma unroll
        for (int ww = 0; ww < 8; ww++) c += scnt[ww * 64 + tid];
        g_pcnt[bid * K + tid] = c;
    }
    // ---- epilogue: mean partials ----
    #pragma unroll
    for (int f = 0; f < 8; f++) {
        int d0 = db + 8 * f + 2 * j2;
        *(float2*)(gp + (kc0 + g) * D + d0)     = make_float2(C2[f][0], C2[f][1]);
        *(float2*)(gp + (kc0 + g + 8) * D + d0) = make_float2(C2[f][2], C2[f][3]);
    }
}

// ---------------------------------------------------------------------------
extern "C" void kernel_launch(void* const* d_in, const int* in_sizes, int n_in,
                              void* d_out, int out_size) {
    const float* embeds = (const float*)d_in[0];
    const float* init   = (const float*)d_in[1];
    int N = in_sizes[0] / D;
    int nT = (N + TILE - 1) / TILE;
    if (nT > NT_MAX) nT = NT_MAX;
    float* out_mu = (float*)d_out;
    float* out_r  = (float*)d_out + K * D;

    cudaFuncSetAttribute(iter_kernel<false>, cudaFuncAttributeMaxDynamicSharedMemorySize, SMEM_TOTAL);
    cudaFuncSetAttribute(iter_kernel<true>,  cudaFuncAttributeMaxDynamicSharedMemorySize, SMEM_TOTAL);

    int rowsPad = nT * TILE;
    prep_kernel<<<(rowsPad + 7) / 8, 256>>>(embeds, N, rowsPad);
    init_mu_kernel<<<K, 128>>>(init);

    for (int it = 0; it < ITERS; it++) {
        int last = (it == ITERS - 1);
        if (last) iter_kernel<true><<<NB, 256, SMEM_TOTAL>>>(out_r, N, nT);
        else      iter_kernel<false><<<NB, 256, SMEM_TOTAL>>>(nullptr, N, nT);
        update_kernel<<<K, 128>>>(last, out_mu);
    }
}

// round 7
// speedup vs baseline: 3.9672x; 1.1061x over previous
#include <cuda_runtime.h>
#include <cuda_bf16.h>
#include <cstdint>

#define D 128
#define K 64
#define TILE 128
#define NT_MAX 1563
#define NB 148
#define TEMP 30.0f
#define EPSn 1e-6f
#define ITERS 11

// smem byte offsets
#define OFF_MU 0                 // MuH 16KB | MuL 16KB
#define OFF_X  32768             // buf0: Xh 32K | Xl 32K ; buf1 at +65536
#define OFF_R  163840            // Rh 16K | Rl 16K
#define OFF_CNT 196608           // 8*64 floats
#define SMEM_TOTAL (OFF_CNT + 2048)

__device__ __align__(16) unsigned char g_x[(size_t)NT_MAX * 65536]; // per tile: Xh 32K | Xl 32K, swizzled
__device__ __align__(16) unsigned char g_mu[32768];                 // MuH 16K | MuL 16K, swizzled
__device__ float g_pmean[NB * K * D];
__device__ float g_pcnt[NB * K];
__device__ float g_mean[K * D];

__device__ __forceinline__ uint32_t smem_u32(const void* p) {
    uint32_t a;
    asm("{ .reg .u64 t; cvta.to.shared.u64 t, %1; cvt.u32.u64 %0, t; }" : "=r"(a) : "l"(p));
    return a;
}
__device__ __forceinline__ void ldsm_x4(uint32_t* r, uint32_t a) {
    asm volatile("ldmatrix.sync.aligned.m8n8.x4.shared.b16 {%0,%1,%2,%3}, [%4];"
        : "=r"(r[0]), "=r"(r[1]), "=r"(r[2]), "=r"(r[3]) : "r"(a));
}
__device__ __forceinline__ void ldsm_x4t(uint32_t* r, uint32_t a) {
    asm volatile("ldmatrix.sync.aligned.m8n8.x4.trans.shared.b16 {%0,%1,%2,%3}, [%4];"
        : "=r"(r[0]), "=r"(r[1]), "=r"(r[2]), "=r"(r[3]) : "r"(a));
}
__device__ __forceinline__ void mma_bf16(float* c, const uint32_t* a, const uint32_t* b) {
    asm volatile("mma.sync.aligned.m16n8k16.row.col.f32.bf16.bf16.f32 "
        "{%0,%1,%2,%3}, {%4,%5,%6,%7}, {%8,%9}, {%0,%1,%2,%3};"
        : "+f"(c[0]), "+f"(c[1]), "+f"(c[2]), "+f"(c[3])
        : "r"(a[0]), "r"(a[1]), "r"(a[2]), "r"(a[3]), "r"(b[0]), "r"(b[1]));
}
__device__ __forceinline__ void cp16(uint32_t dst, const void* src) {
    asm volatile("cp.async.cg.shared.global [%0], [%1], 16;" :: "r"(dst), "l"(src) : "memory");
}
#define CP_COMMIT() asm volatile("cp.async.commit_group;" ::: "memory")
#define CP_WAIT0()  asm volatile("cp.async.wait_group 0;" ::: "memory")

__device__ __forceinline__ uint32_t pack_bf16x2(__nv_bfloat16 a, __nv_bfloat16 b) {
    __nv_bfloat162 v(a, b);
    return *(uint32_t*)&v;
}

// ---------------------------------------------------------------------------
__global__ void prep_kernel(const float* __restrict__ x, int N, int rowsPad) {
    int w = (blockIdx.x * blockDim.x + threadIdx.x) >> 5;
    int lane = threadIdx.x & 31;
    if (w >= rowsPad) return;
    float4 v = make_float4(0.f, 0.f, 0.f, 0.f);
    if (w < N) {
        v = ((const float4*)(x + (size_t)w * D))[lane];
        float ss = v.x*v.x + v.y*v.y + v.z*v.z + v.w*v.w;
        #pragma unroll
        for (int o = 16; o > 0; o >>= 1) ss += __shfl_xor_sync(0xffffffffu, ss, o);
        float inv = 1.0f / (sqrtf(ss) + EPSn);
        v.x *= inv; v.y *= inv; v.z *= inv; v.w *= inv;
    }
    float f[4] = {v.x, v.y, v.z, v.w};
    __nv_bfloat16 h[4], lo[4];
    #pragma unroll
    for (int i = 0; i < 4; i++) {
        h[i]  = __float2bfloat16(f[i]);
        lo[i] = __float2bfloat16(f[i] - __bfloat162float(h[i]));
    }
    uint2 uh, ul;
    uh.x = pack_bf16x2(h[0], h[1]);  uh.y = pack_bf16x2(h[2], h[3]);
    ul.x = pack_bf16x2(lo[0], lo[1]); ul.y = pack_bf16x2(lo[2], lo[3]);
    int t = w >> 7, rl = w & 127, d0 = lane * 4;
    uint32_t off = (uint32_t)rl * 256 + ((((d0 >> 3) ^ (rl & 7)) & 15) << 4) + ((d0 & 7) << 1);
    unsigned char* base = g_x + (size_t)t * 65536;
    *(uint2*)(base + off)         = uh;
    *(uint2*)(base + 32768 + off) = ul;
}

// ---------------------------------------------------------------------------
__device__ __forceinline__ void write_mu(int k, int d, float nv) {
    __nv_bfloat16 h = __float2bfloat16(nv);
    __nv_bfloat16 l = __float2bfloat16(nv - __bfloat162float(h));
    uint32_t off = (uint32_t)k * 256 + ((((d >> 3) ^ (k & 7)) & 15) << 4) + ((d & 7) << 1);
    *(__nv_bfloat16*)(g_mu + off)         = h;
    *(__nv_bfloat16*)(g_mu + 16384 + off) = l;
}

__global__ void init_mu_kernel(const float* __restrict__ init) {
    int k = blockIdx.x, d = threadIdx.x;
    float v = init[k * D + d];
    __shared__ float sred[4];
    float ss = v * v;
    #pragma unroll
    for (int o = 16; o > 0; o >>= 1) ss += __shfl_xor_sync(0xffffffffu, ss, o);
    if ((d & 31) == 0) sred[d >> 5] = ss;
    __syncthreads();
    float tot = sred[0] + sred[1] + sred[2] + sred[3];
    write_mu(k, d, v / (sqrtf(tot) + EPSn));
}

// ---------------------------------------------------------------------------
// Parallel partial-mean reduction: 8 lanes per (k,d), each sums 18-19 values.
__global__ void reduce_mean_kernel() {
    int gidx = blockIdx.x * 256 + threadIdx.x;   // 65536 threads
    int i = gidx >> 3, part = gidx & 7;
    const float* p = g_pmean + i;
    float s = 0.0f;
    #pragma unroll
    for (int j = 0; j < 18; j++)
        s += p[(size_t)(part + j * 8) * (K * D)];
    if (part < NB - 144)
        s += p[(size_t)(part + 144) * (K * D)];
    s += __shfl_xor_sync(0xffffffffu, s, 1);
    s += __shfl_xor_sync(0xffffffffu, s, 2);
    s += __shfl_xor_sync(0xffffffffu, s, 4);
    if (part == 0) g_mean[i] = s;
}

__global__ void update_kernel(int last, float* __restrict__ mu_out) {
    int k = blockIdx.x, d = threadIdx.x;
    __shared__ float swred[4];
    __shared__ float sred[4];
    // parallel cnt reduce
    float c = 0.0f;
    for (int b = d; b < NB; b += 128) c += g_pcnt[b * K + k];
    #pragma unroll
    for (int o = 16; o > 0; o >>= 1) c += __shfl_xor_sync(0xffffffffu, c, o);
    if ((d & 31) == 0) swred[d >> 5] = c;
    __syncthreads();
    float cs = swred[0] + swred[1] + swred[2] + swred[3];
    float v = g_mean[k * D + d] / cs;
    float ss = v * v;
    #pragma unroll
    for (int o = 16; o > 0; o >>= 1) ss += __shfl_xor_sync(0xffffffffu, ss, o);
    if ((d & 31) == 0) sred[d >> 5] = ss;
    __syncthreads();
    float tot = sred[0] + sred[1] + sred[2] + sred[3];
    if (last) mu_out[k * D + d] = v;
    else      write_mu(k, d, v / (sqrtf(tot) + EPSn));
}

// ---------------------------------------------------------------------------
template<bool LAST>
__global__ void __launch_bounds__(256, 1) iter_kernel(float* __restrict__ r_out,
                                                      int N, int nT) {
    extern __shared__ unsigned char sm[];
    int tid = threadIdx.x, w = tid >> 5, lane = tid & 31;
    int bid = blockIdx.x;
    int t0 = (int)((long long)bid * nT / gridDim.x);
    int t1 = (int)((long long)(bid + 1) * nT / gridDim.x);
    float* gp = g_pmean + (size_t)bid * K * D;
    if (t0 >= t1) {
        for (int i = tid; i < K * D; i += 256) gp[i] = 0.0f;
        if (tid < K) g_pcnt[bid * K + tid] = 0.0f;
        return;
    }
    uint32_t sb = smem_u32(sm);
    uint32_t sMuH = sb + OFF_MU;
    uint32_t sR   = sb + OFF_R;
    float* scnt = (float*)(sm + OFF_CNT);

    // stage Mu (32KB) + X(t0) (64KB)
    #pragma unroll
    for (int j = 0; j < 8; j++)
        cp16(sMuH + (tid + 256 * j) * 16, g_mu + (tid + 256 * j) * 16);
    {
        const unsigned char* gx = g_x + (size_t)t0 * 65536;
        #pragma unroll
        for (int j = 0; j < 16; j++)
            cp16(sb + OFF_X + (tid + 256 * j) * 16, gx + (tid + 256 * j) * 16);
    }
    CP_COMMIT(); CP_WAIT0();
    __syncthreads();

    float C2[8][4];
    #pragma unroll
    for (int f = 0; f < 8; f++)
        #pragma unroll
        for (int q = 0; q < 4; q++) C2[f][q] = 0.0f;
    float cacc[16];
    #pragma unroll
    for (int j = 0; j < 16; j++) cacc[j] = 0.0f;

    int m0  = w * 16;                       // GEMM1 row strip
    int kc0 = (w & 3) * 16;                 // GEMM2 cluster strip
    int db  = (w >> 2) * 64;                // GEMM2 d half
    int g = lane >> 2, j2 = lane & 3;

    for (int t = t0; t < t1; t++) {
        int buf = (t - t0) & 1;
        uint32_t sX = sb + OFF_X + buf * 65536;       // Xh; Xl at +32768
        if (t + 1 < t1) {
            const unsigned char* gx = g_x + (size_t)(t + 1) * 65536;
            uint32_t dst = sb + OFF_X + (buf ^ 1) * 65536;
            #pragma unroll
            for (int j = 0; j < 16; j++)
                cp16(dst + (tid + 256 * j) * 16, gx + (tid + 256 * j) * 16);
        }
        CP_COMMIT();

        // ---- GEMM1: C1[16 rows x 64 kc] = X . Mu^T (3-term split) ----
        float C1[8][4];
        #pragma unroll
        for (int f = 0; f < 8; f++)
            #pragma unroll
            for (int q = 0; q < 4; q++) C1[f][q] = 0.0f;
        #pragma unroll
        for (int ks = 0; ks < 8; ks++) {
            uint32_t ah[4], al[4];
            int ar = m0 + (lane & 15);
            int ac = ks * 16 + ((lane >> 4) << 3);
            uint32_t aaddr = sX + (uint32_t)ar * 256 + ((((ac >> 3) ^ (ar & 7)) & 15) << 4);
            ldsm_x4(ah, aaddr);
            ldsm_x4(al, aaddr + 32768);
            #pragma unroll
            for (int fp = 0; fp < 4; fp++) {
                int brow = 16 * fp + ((lane >> 4) << 3) + (lane & 7);
                int bc = ks * 16 + (((lane >> 3) & 1) << 3);
                uint32_t baddr = sMuH + (uint32_t)brow * 256 + ((((bc >> 3) ^ (brow & 7)) & 15) << 4);
                uint32_t bh4[4], bl4[4];
                ldsm_x4(bh4, baddr);
                ldsm_x4(bl4, baddr + 16384);
                mma_bf16(C1[2*fp],   ah, bh4);
                mma_bf16(C1[2*fp],   al, bh4);
                mma_bf16(C1[2*fp],   ah, bl4);
                mma_bf16(C1[2*fp+1], ah, bh4 + 2);
                mma_bf16(C1[2*fp+1], al, bh4 + 2);
                mma_bf16(C1[2*fp+1], ah, bl4 + 2);
            }
        }

        // ---- softmax (max-free; |logit| <= ~30) ----
        int grow0 = t * TILE + m0 + g;
        int grow1 = grow0 + 8;
        float s0 = 0.0f, s1 = 0.0f;
        #pragma unroll
        for (int f = 0; f < 8; f++) {
            #pragma unroll
            for (int q = 0; q < 4; q++) C1[f][q] = __expf(TEMP * C1[f][q]);
            s0 += C1[f][0] + C1[f][1];
            s1 += C1[f][2] + C1[f][3];
        }
        s0 += __shfl_xor_sync(0xffffffffu, s0, 1); s0 += __shfl_xor_sync(0xffffffffu, s0, 2);
        s1 += __shfl_xor_sync(0xffffffffu, s1, 1); s1 += __shfl_xor_sync(0xffffffffu, s1, 2);
        float inv0 = (grow0 < N) ? 1.0f / s0 : 0.0f;
        float inv1 = (grow1 < N) ? 1.0f / s1 : 0.0f;
        int row0 = m0 + g, row1 = row0 + 8;
        #pragma unroll
        for (int f = 0; f < 8; f++) {
            float r0a = C1[f][0] * inv0, r0b = C1[f][1] * inv0;
            float r1a = C1[f][2] * inv1, r1b = C1[f][3] * inv1;
            cacc[2*f]   += r0a + r1a;
            cacc[2*f+1] += r0b + r1b;
            int kc = 8 * f + 2 * j2;
            {
                __nv_bfloat16 ha = __float2bfloat16(r0a), hb = __float2bfloat16(r0b);
                __nv_bfloat16 la = __float2bfloat16(r0a - __bfloat162float(ha));
                __nv_bfloat16 lb = __float2bfloat16(r0b - __bfloat162float(hb));
                uint32_t off = (uint32_t)row0 * 128 + (((f ^ (row0 & 7)) & 7) << 4) + (j2 << 2);
                *(uint32_t*)(sm + OFF_R + off)         = pack_bf16x2(ha, hb);
                *(uint32_t*)(sm + OFF_R + 16384 + off) = pack_bf16x2(la, lb);
            }
            {
                __nv_bfloat16 ha = __float2bfloat16(r1a), hb = __float2bfloat16(r1b);
                __nv_bfloat16 la = __float2bfloat16(r1a - __bfloat162float(ha));
                __nv_bfloat16 lb = __float2bfloat16(r1b - __bfloat162float(hb));
                uint32_t off = (uint32_t)row1 * 128 + (((f ^ (row1 & 7)) & 7) << 4) + (j2 << 2);
                *(uint32_t*)(sm + OFF_R + off)         = pack_bf16x2(ha, hb);
                *(uint32_t*)(sm + OFF_R + 16384 + off) = pack_bf16x2(la, lb);
            }
            if (LAST) {
                if (grow0 < N) *(float2*)(r_out + (size_t)grow0 * K + kc) = make_float2(r0a, r0b);
                if (grow1 < N) *(float2*)(r_out + (size_t)grow1 * K + kc) = make_float2(r1a, r1b);
            }
        }
        __syncthreads();

        // ---- GEMM2: C2[16 kc x 64 d] += R^T . X (3-term split) ----
        #pragma unroll
        for (int ks = 0; ks < 8; ks++) {
            int row0k = ks * 16;
            uint32_t ah[4], al[4];
            int arm = row0k + (lane & 7) + ((lane >> 4) << 3);
            int acm = kc0 + ((lane >> 3) & 1) * 8;
            uint32_t aaddr = sR + (uint32_t)arm * 128 + ((((acm >> 3) ^ (arm & 7)) & 7) << 4);
            ldsm_x4t(ah, aaddr);
            ldsm_x4t(al, aaddr + 16384);
            #pragma unroll
            for (int fp = 0; fp < 4; fp++) {
                int brm = row0k + (((lane >> 3) & 1) << 3) + (lane & 7);
                int d0c = db + 16 * fp + ((lane >> 4) << 3);
                uint32_t baddr = sX + (uint32_t)brm * 256 + ((((d0c >> 3) ^ (brm & 7)) & 15) << 4);
                uint32_t bh4[4], bl4[4];
                ldsm_x4t(bh4, baddr);
                ldsm_x4t(bl4, baddr + 32768);
                mma_bf16(C2[2*fp],   ah, bh4);
                mma_bf16(C2[2*fp],   al, bh4);
                mma_bf16(C2[2*fp],   ah, bl4);
                mma_bf16(C2[2*fp+1], ah, bh4 + 2);
                mma_bf16(C2[2*fp+1], al, bh4 + 2);
                mma_bf16(C2[2*fp+1], ah, bl4 + 2);
            }
        }
        CP_WAIT0();
        __syncthreads();
    }

    // ---- epilogue: counts ----
    #pragma unroll
    for (int j = 0; j < 16; j++) {
        cacc[j] += __shfl_xor_sync(0xffffffffu, cacc[j], 4);
        cacc[j] += __shfl_xor_sync(0xffffffffu, cacc[j], 8);
        cacc[j] += __shfl_xor_sync(0xffffffffu, cacc[j], 16);
    }
    if (lane < 4) {
        #pragma unroll
        for (int f = 0; f < 8; f++) {
            scnt[w * 64 + 8 * f + 2 * lane]     = cacc[2*f];
            scnt[w * 64 + 8 * f + 2 * lane + 1] = cacc[2*f+1];
        }
    }
    __syncthreads();
    if (tid < K) {
        float c = 0.0f;
        #pragma unroll
        for (int ww = 0; ww < 8; ww++) c += scnt[ww * 64 + tid];
        g_pcnt[bid * K + tid] = c;
    }
    // ---- epilogue: mean partials ----
    #pragma unroll
    for (int f = 0; f < 8; f++) {
        int d0 = db + 8 * f + 2 * j2;
        *(float2*)(gp + (kc0 + g) * D + d0)     = make_float2(C2[f][0], C2[f][1]);
        *(float2*)(gp + (kc0 + g + 8) * D + d0) = make_float2(C2[f][2], C2[f][3]);
    }
}

// ---------------------------------------------------------------------------
extern "C" void kernel_launch(void* const* d_in, const int* in_sizes, int n_in,
                              void* d_out, int out_size) {
    const float* embeds = (const float*)d_in[0];
    const float* init   = (const float*)d_in[1];
    int N = in_sizes[0] / D;
    int nT = (N + TILE - 1) / TILE;
    if (nT > NT_MAX) nT = NT_MAX;
    float* out_mu = (float*)d_out;
    float* out_r  = (float*)d_out + K * D;

    cudaFuncSetAttribute(iter_kernel<false>, cudaFuncAttributeMaxDynamicSharedMemorySize, SMEM_TOTAL);
    cudaFuncSetAttribute(iter_kernel<true>,  cudaFuncAttributeMaxDynamicSharedMemorySize, SMEM_TOTAL);

    int rowsPad = nT * TILE;
    prep_kernel<<<(rowsPad + 7) / 8, 256>>>(embeds, N, rowsPad);
    init_mu_kernel<<<K, 128>>>(init);

    for (int it = 0; it < ITERS; it++) {
        int last = (it == ITERS - 1);
        if (last) iter_kernel<true><<<NB, 256, SMEM_TOTAL>>>(out_r, N, nT);
        else      iter_kernel<false><<<NB, 256, SMEM_TOTAL>>>(nullptr, N, nT);
        reduce_mean_kernel<<<256, 256>>>();
        update_kernel<<<K, 128>>>(last, out_mu);
    }
}